// round 8
// baseline (speedup 1.0000x reference)
#include <cuda_runtime.h>
#include <cuda_bf16.h>
#include <math_constants.h>

#define D       32000
#define NROWS   4096
#define TA      256
#define NWARP   8
#define NCH     8               // chunks per row
#define CHF4    1000            // float4 per chunk (block-wide)
#define WF4     125             // float4 per warp per chunk
#define WCAP    512             // per-warp coarse-candidate capacity (pow2)
#define NBIS    8
#define NNEWT   4
#define XT      1.5f            // coarse threshold (X scale); valid iff rowmaxX > XT+2 (checked)
#define CHI     0.005590169943749474f   // (1/32000)^0.5

__device__ float g_loss[NROWS];
__device__ int   g_done;        // zero-init; last block resets (graph-replay safe)

__device__ __forceinline__ float warp_sum(float v) {
    #pragma unroll
    for (int o = 16; o; o >>= 1) v += __shfl_xor_sync(0xffffffffu, v, o);
    return v;
}
__device__ __forceinline__ float warp_max(float v) {
    #pragma unroll
    for (int o = 16; o; o >>= 1) v = fmaxf(v, __shfl_xor_sync(0xffffffffu, v, o));
    return v;
}

__device__ __forceinline__ void cp16(float4* smem, const float4* gmem) {
    unsigned s = (unsigned)__cvta_generic_to_shared(smem);
    asm volatile("cp.async.cg.shared.global [%0], [%1], 16;\n" :: "r"(s), "l"(gmem));
}
#define CP_COMMIT()  asm volatile("cp.async.commit_group;\n" ::: "memory")
#define CP_WAIT(n)   asm volatile("cp.async.wait_group %0;\n" :: "n"(n) : "memory")

#define FOR16(OP) OP(c0.x) OP(c0.y) OP(c0.z) OP(c0.w) \
                  OP(c1.x) OP(c1.y) OP(c1.z) OP(c1.w) \
                  OP(c2.x) OP(c2.y) OP(c2.z) OP(c2.w) \
                  OP(c3.x) OP(c3.y) OP(c3.z) OP(c3.w)

extern __shared__ float4 s_stage[];          // 2 * CHF4 float4 = 32000 B (double buffer)

__global__ void __launch_bounds__(TA, 4) fused_kernel(const float* __restrict__ X,
                                                      const int*   __restrict__ target,
                                                      float*       __restrict__ out)
{
    __shared__ float s_buf[NWARP][WCAP];     // 16 KB coarse candidates (Xa scale)
    __shared__ float s_F[2][NWARP], s_G[2][NWARP];
    __shared__ float s_p3[3][NWARP];
    __shared__ float s_max[NWARP];
    __shared__ int   s_fb;
    __shared__ int   s_last;

    const int row  = blockIdx.x;
    const int tid  = threadIdx.x;
    const int lane = tid & 31;
    const int wid  = tid >> 5;

    if (tid == 0) s_fb = 0;
    __syncthreads();

    const float4* __restrict__ Xr4 = reinterpret_cast<const float4*>(X + (size_t)row * D);
    const float*  __restrict__ Xr  = X + (size_t)row * D;

    float xt = 0.f;
    if (tid == 0) xt = Xr[target[row]];

    const bool has4 = (lane + 96) < WF4;     // lanes 29..31 own only 3 float4s

    // issue one chunk's per-warp region; each lane copies EXACTLY the slots it reads
    #define ISSUE(ch) do {                                                   \
        const float4* _s = Xr4 + (ch) * CHF4 + wid * WF4;                    \
        float4* _d = s_stage + ((ch) & 1) * CHF4 + wid * WF4;                \
        cp16(_d + lane,      _s + lane);                                     \
        cp16(_d + lane + 32, _s + lane + 32);                                \
        cp16(_d + lane + 64, _s + lane + 64);                                \
        if (has4) cp16(_d + lane + 96, _s + lane + 96);                      \
        CP_COMMIT();                                                         \
    } while (0)

    // ============ cp.async pipelined filter (R6 ballot compaction, barrier-free) ===========
    ISSUE(0);
    int k = 0;
    const float4 FILL = make_float4(-CUDART_INF_F, -CUDART_INF_F, -CUDART_INF_F, -CUDART_INF_F);

    #pragma unroll 1
    for (int ch = 0; ch < NCH; ch++) {
        if (ch + 1 < NCH) { ISSUE(ch + 1); CP_WAIT(1); }
        else              { CP_WAIT(0); }

        const float4* buf = s_stage + (ch & 1) * CHF4 + wid * WF4;
        float4 c0 = buf[lane];
        float4 c1 = buf[lane + 32];
        float4 c2 = buf[lane + 64];
        float4 c3 = has4 ? buf[lane + 96] : FILL;

        int ks = 0;
        #define CNT(a) ks += ((a) > XT);
        FOR16(CNT)
        #undef CNT

        int inc = ks;
        #pragma unroll
        for (int o = 1; o < 32; o <<= 1) {
            int n = __shfl_up_sync(0xffffffffu, inc, o);
            if (lane >= o) inc += n;
        }
        int o = k + (inc - ks);
        #define WR(a) { bool p = (a) > XT;                                   \
                        if (p) s_buf[wid][o & (WCAP - 1)] = 0.5f * (a);      \
                        o += p; }
        FOR16(WR)
        #undef WR
        k += __shfl_sync(0xffffffffu, inc, 31);
    }
    #undef ISSUE

    if (k > WCAP) s_fb = 1;                  // benign race; wrapped buffer triggers fallback
    __syncwarp();                            // order all lanes' STS before cross-lane LDS

    // ---- candidate max (row max always passes the filter when threshold valid) ----
    {
        const int kk = (k < WCAP) ? k : WCAP;
        float cm = -CUDART_INF_F;
        for (int i = lane; i < kk; i += 32) cm = fmaxf(cm, s_buf[wid][i]);
        cm = warp_max(cm);
        if (lane == 0) s_max[wid] = cm;      // Xa scale
    }
    __syncthreads();

    float rmax = s_max[0];
    #pragma unroll
    for (int w = 1; w < NWARP; w++) rmax = fmaxf(rmax, s_max[w]);
    const bool fb = (s_fb != 0) || !(2.0f * rmax - 2.0f > XT + 1e-4f);

    if (fb) {    // rare: recompute exact row max block-wide from global
        __syncthreads();
        float m = -CUDART_INF_F;
        for (int i = tid; i < D; i += TA) m = fmaxf(m, Xr[i]);
        m = warp_max(m);
        if (lane == 0) s_max[wid] = m;
        __syncthreads();
        float mm = s_max[0];
        #pragma unroll
        for (int w = 1; w < NWARP; w++) mm = fmaxf(mm, s_max[w]);
        rmax = 0.5f * mm;
    }

    // ============ prune to true candidates (Xa > rmax-1) in place ==========================
    int cnt = 0;
    if (!fb) {
        const float tpa = rmax - 1.0f - 5e-6f;   // margin only adds zero-contributing elems
        const int kk = (k < WCAP) ? k : WCAP;
        const int nb = (kk + 31) >> 5;
        for (int j = 0; j < nb; j++) {
            int i = 32 * j + lane;
            float v = (i < kk) ? s_buf[wid][i] : -CUDART_INF_F;
            bool pred = v > tpa;
            unsigned m = __ballot_sync(0xffffffffu, pred);
            if (pred) s_buf[wid][cnt + __popc(m & ((1u << lane) - 1u))] = v;
            cnt += __popc(m);
        }
    }

    // ============ solve: 8 bisection + 4 safeguarded Newton =================================
    const float tau_lo0 = rmax - 1.0f;
    const float tau_hi  = rmax - CHI;
    float tau_lo = tau_lo0;
    float dm = tau_hi - tau_lo;
    float tau_m = tau_lo;
    int pb = 0;

    #pragma unroll 1
    for (int it = 0; it < NBIS + NNEWT; it++) {
        const bool newton = (it >= NBIS);
        float te;
        if (!newton) { dm *= 0.5f; te = tau_lo + dm; }
        else         { te = tau_m; }

        float F = 0.f, G = 0.f;
        if (!fb) {
            #pragma unroll 4
            for (int i = lane; i < cnt; i += 32) {
                float t = fmaxf(s_buf[wid][i] - te, 0.f);
                F = fmaf(t, t, F); G += t;
            }
        } else {
            for (int i = tid; i < D; i += TA) {
                float t = fmaxf(0.5f * Xr[i] - te, 0.f);
                F = fmaf(t, t, F); G += t;
            }
        }
        #pragma unroll
        for (int o = 16; o; o >>= 1) {
            F += __shfl_xor_sync(0xffffffffu, F, o);
            G += __shfl_xor_sync(0xffffffffu, G, o);
        }
        if (lane == 0) { s_F[pb][wid] = F; s_G[pb][wid] = G; }
        __syncthreads();
        float Ft = 0.f, Gt = 0.f;
        #pragma unroll
        for (int w = 0; w < NWARP; w++) { Ft += s_F[pb][w]; Gt += s_G[pb][w]; }
        const float f = Ft - 1.0f;

        if (!newton) {
            if (f >= 0.f) tau_lo = te;        // f(tau_lo) >= 0 invariant
            if (it == NBIS - 1) tau_m = tau_lo;
        } else {
            float tn = te + f / (2.0f * Gt);  // f' = -2G; Gt > 0 on bracket
            tau_m = fminf(fmaxf(tn, tau_lo0), tau_hi);
        }
        pb ^= 1;
    }

    // ============ final stats at tau_m ======================================================
    float S = 0.f, A15 = 0.f, PX = 0.f;
    if (!fb) {
        #pragma unroll 4
        for (int i = lane; i < cnt; i += 32) {
            float v = s_buf[wid][i];
            float t = fmaxf(v - tau_m, 0.f);
            float pr = t * t;
            S += pr; A15 = fmaf(pr, t, A15); PX = fmaf(pr, v, PX);
        }
    } else {
        for (int i = tid; i < D; i += TA) {
            float v = 0.5f * Xr[i];
            float t = fmaxf(v - tau_m, 0.f);
            float pr = t * t;
            S += pr; A15 = fmaf(pr, t, A15); PX = fmaf(pr, v, PX);
        }
    }
    S = warp_sum(S); A15 = warp_sum(A15); PX = warp_sum(PX);
    if (lane == 0) { s_p3[0][wid] = S; s_p3[1][wid] = A15; s_p3[2][wid] = PX; }
    __syncthreads();

    if (tid == 0) {
        float St = 0.f, At = 0.f, Pt = 0.f;
        #pragma unroll
        for (int w = 0; w < NWARP; w++) { St += s_p3[0][w]; At += s_p3[1][w]; Pt += s_p3[2][w]; }
        float sum_p15 = At / (St * sqrtf(St));
        float omega   = (1.0f - sum_p15) / 0.75f;      // alpha*(alpha-1) = 0.75
        g_loss[row] = omega + 2.0f * Pt / St - xt;

        __threadfence();
        int t = atomicAdd(&g_done, 1);
        s_last = (t == NROWS - 1);
    }
    __syncthreads();

    // ============ last block: deterministic mean ============================================
    if (s_last) {
        if (tid == 0) g_done = 0;
        __threadfence();
        float a = 0.f;
        #pragma unroll 4
        for (int i = tid; i < NROWS; i += TA) a += g_loss[i];
        a = warp_sum(a);
        if (lane == 0) s_p3[0][wid] = a;
        __syncthreads();
        if (tid == 0) {
            float tot = 0.f;
            #pragma unroll
            for (int w = 0; w < NWARP; w++) tot += s_p3[0][w];
            out[0] = tot / (float)NROWS;
        }
    }
}

// ============================================================================
extern "C" void kernel_launch(void* const* d_in, const int* in_sizes, int n_in,
                              void* d_out, int out_size)
{
    const float* X      = (const float*)d_in[0];
    const int*   target = (const int*)  d_in[1];
    float*       out    = (float*)d_out;

    const int dynsmem = 2 * CHF4 * (int)sizeof(float4);   // 32000 B staging
    cudaFuncSetAttribute(fused_kernel, cudaFuncAttributeMaxDynamicSharedMemorySize, dynsmem);

    fused_kernel<<<NROWS, TA, dynsmem>>>(X, target, out);
}

// round 9
// speedup vs baseline: 1.6692x; 1.6692x over previous
#include <cuda_runtime.h>
#include <cuda_bf16.h>
#include <math_constants.h>

#define D       32000
#define D4      8000
#define NROWS   4096
#define TA      256
#define NWARP   8
#define CHUNK4  1000            // float4s per warp chunk
#define SUBF4   125             // float4s per sub-step
#define NSUB    8
#define WCAP    512             // per-warp coarse-candidate capacity (pow2; exp 267, +15 sigma)
#define NBIS    5
#define NNEWT   4
#define XT      1.5f            // coarse threshold (X scale); valid iff rowmaxX > XT+2 (checked)
#define CHI     0.005590169943749474f   // (1/32000)^0.5

__device__ float g_loss[NROWS];
__device__ int   g_done;        // zero-init; last block resets (graph-replay safe)

__device__ __forceinline__ float warp_sum(float v) {
    #pragma unroll
    for (int o = 16; o; o >>= 1) v += __shfl_xor_sync(0xffffffffu, v, o);
    return v;
}
__device__ __forceinline__ float warp_max(float v) {
    #pragma unroll
    for (int o = 16; o; o >>= 1) v = fmaxf(v, __shfl_xor_sync(0xffffffffu, v, o));
    return v;
}

#define FOR16(OP) OP(c0.x) OP(c0.y) OP(c0.z) OP(c0.w) \
                  OP(c1.x) OP(c1.y) OP(c1.z) OP(c1.w) \
                  OP(c2.x) OP(c2.y) OP(c2.z) OP(c2.w) \
                  OP(c3.x) OP(c3.y) OP(c3.z) OP(c3.w)

__global__ void __launch_bounds__(TA, 5) fused_kernel(const float* __restrict__ X,
                                                      const int*   __restrict__ target,
                                                      float*       __restrict__ out)
{
    __shared__ float s_buf[NWARP][WCAP];     // 16 KB coarse candidates (raw X scale)
    __shared__ float s_F[2][NWARP], s_G[2][NWARP];
    __shared__ float s_p3[3][NWARP];
    __shared__ float s_max[NWARP];
    __shared__ int   s_fb;
    __shared__ int   s_last;

    const int row  = blockIdx.x;
    const int tid  = threadIdx.x;
    const int lane = tid & 31;
    const int wid  = tid >> 5;

    if (tid == 0) s_fb = 0;
    __syncthreads();

    const float4* __restrict__ Xr4 = reinterpret_cast<const float4*>(X + (size_t)row * D);
    const float*  __restrict__ Xr  = X + (size_t)row * D;
    const float4* __restrict__ W4  = Xr4 + wid * CHUNK4;

    float xt = 0.f;
    if (tid == 0) xt = Xr[target[row]];

    // ============ single-pass filter: constant threshold, raw-X stores =====================
    const float4 FILL = make_float4(-CUDART_INF_F, -CUDART_INF_F, -CUDART_INF_F, -CUDART_INF_F);
    #define LOADSUB(dst0,dst1,dst2,dst3,sub) do {                        \
        int _b = (sub) * SUBF4;                                          \
        dst0 = W4[_b + lane];                                            \
        dst1 = W4[_b + lane + 32];                                       \
        dst2 = W4[_b + lane + 64];                                       \
        dst3 = (lane + 96 < SUBF4) ? W4[_b + lane + 96] : FILL;          \
    } while (0)

    float4 a0, a1, a2, a3, b0, b1, b2, b3;
    LOADSUB(a0, a1, a2, a3, 0);
    LOADSUB(b0, b1, b2, b3, 1);

    int k = 0;
    #pragma unroll
    for (int sub = 0; sub < NSUB; sub++) {
        float4 c0 = a0, c1 = a1, c2 = a2, c3 = a3;
        a0 = b0; a1 = b1; a2 = b2; a3 = b3;
        if (sub + 2 < NSUB) LOADSUB(b0, b1, b2, b3, sub + 2);

        int ks = 0;
        #define CNT(a) ks += ((a) > XT);
        FOR16(CNT)
        #undef CNT

        int inc = ks;
        #pragma unroll
        for (int o = 1; o < 32; o <<= 1) {
            int n = __shfl_up_sync(0xffffffffu, inc, o);
            if (lane >= o) inc += n;
        }
        int o = k + (inc - ks);
        #define WR(a) { bool p = (a) > XT;                                   \
                        if (p) s_buf[wid][o & (WCAP - 1)] = (a);             \
                        o += p; }
        FOR16(WR)
        #undef WR
        k += __shfl_sync(0xffffffffu, inc, 31);
    }
    #undef LOADSUB

    if (k > WCAP) s_fb = 1;                  // benign race; wrapped buffer triggers fallback
    __syncwarp();                            // order all lanes' STS before cross-lane LDS

    // ---- candidate max, X scale (row max always passes the filter when threshold valid) ----
    {
        const int kk = (k < WCAP) ? k : WCAP;
        float cm = -CUDART_INF_F;
        for (int i = lane; i < kk; i += 32) cm = fmaxf(cm, s_buf[wid][i]);
        cm = warp_max(cm);
        if (lane == 0) s_max[wid] = cm;
    }
    __syncthreads();

    float rmaxX = s_max[0];
    #pragma unroll
    for (int w = 1; w < NWARP; w++) rmaxX = fmaxf(rmaxX, s_max[w]);
    const bool fb = (s_fb != 0) || !(rmaxX - 2.0f > XT + 1e-4f);

    if (fb) {    // rare: recompute exact row max block-wide
        __syncthreads();
        float m = -CUDART_INF_F;
        for (int i = tid; i < D; i += TA) m = fmaxf(m, Xr[i]);
        m = warp_max(m);
        if (lane == 0) s_max[wid] = m;
        __syncthreads();
        rmaxX = s_max[0];
        #pragma unroll
        for (int w = 1; w < NWARP; w++) rmaxX = fmaxf(rmaxX, s_max[w]);
    }
    const float rmax = 0.5f * rmaxX;         // exact: max(Xa) = 0.5*max(X)

    // ============ prune to true candidates (X > rmaxX-2), scale to Xa ======================
    int cnt = 0;
    if (!fb) {
        const float tX = rmaxX - 2.0f - 1e-5f;   // margin only adds zero-contributing elems
        const int kk = (k < WCAP) ? k : WCAP;
        const int nb = (kk + 31) >> 5;
        for (int j = 0; j < nb; j++) {
            int i = 32 * j + lane;
            float v = (i < kk) ? s_buf[wid][i] : -CUDART_INF_F;
            bool pred = v > tX;
            unsigned m = __ballot_sync(0xffffffffu, pred);
            if (pred) s_buf[wid][cnt + __popc(m & ((1u << lane) - 1u))] = 0.5f * v;
            cnt += __popc(m);
        }
    }

    // ============ solve: 5 bisection + 4 safeguarded Newton =================================
    const float tau_lo0 = rmax - 1.0f;
    const float tau_hi  = rmax - CHI;
    float tau_lo = tau_lo0;
    float dm = tau_hi - tau_lo;
    float tau_m = tau_lo;
    int pb = 0;

    #pragma unroll 1
    for (int it = 0; it < NBIS + NNEWT; it++) {
        const bool newton = (it >= NBIS);
        float te;
        if (!newton) { dm *= 0.5f; te = tau_lo + dm; }
        else         { te = tau_m; }

        float F = 0.f, G = 0.f;
        if (!fb) {
            #pragma unroll 4
            for (int i = lane; i < cnt; i += 32) {
                float t = fmaxf(s_buf[wid][i] - te, 0.f);
                F = fmaf(t, t, F); G += t;
            }
        } else {
            for (int i = tid; i < D; i += TA) {
                float t = fmaxf(0.5f * Xr[i] - te, 0.f);
                F = fmaf(t, t, F); G += t;
            }
        }
        #pragma unroll
        for (int o = 16; o; o >>= 1) {
            F += __shfl_xor_sync(0xffffffffu, F, o);
            G += __shfl_xor_sync(0xffffffffu, G, o);
        }
        if (lane == 0) { s_F[pb][wid] = F; s_G[pb][wid] = G; }
        __syncthreads();
        float Ft = 0.f, Gt = 0.f;
        #pragma unroll
        for (int w = 0; w < NWARP; w++) { Ft += s_F[pb][w]; Gt += s_G[pb][w]; }
        const float f = Ft - 1.0f;

        if (!newton) {
            if (f >= 0.f) tau_lo = te;        // f(tau_lo) >= 0 invariant
            if (it == NBIS - 1) tau_m = tau_lo;
        } else {
            float tn = te + f / (2.0f * Gt);  // f' = -2G; convex f: Newton from left stays left
            tau_m = fminf(fmaxf(tn, tau_lo0), tau_hi);
        }
        pb ^= 1;
    }

    // ============ final stats at tau_m ======================================================
    float S = 0.f, A15 = 0.f, PX = 0.f;
    if (!fb) {
        #pragma unroll 4
        for (int i = lane; i < cnt; i += 32) {
            float v = s_buf[wid][i];
            float t = fmaxf(v - tau_m, 0.f);
            float pr = t * t;
            S += pr; A15 = fmaf(pr, t, A15); PX = fmaf(pr, v, PX);
        }
    } else {
        for (int i = tid; i < D; i += TA) {
            float v = 0.5f * Xr[i];
            float t = fmaxf(v - tau_m, 0.f);
            float pr = t * t;
            S += pr; A15 = fmaf(pr, t, A15); PX = fmaf(pr, v, PX);
        }
    }
    S = warp_sum(S); A15 = warp_sum(A15); PX = warp_sum(PX);
    if (lane == 0) { s_p3[0][wid] = S; s_p3[1][wid] = A15; s_p3[2][wid] = PX; }
    __syncthreads();

    if (tid == 0) {
        float St = 0.f, At = 0.f, Pt = 0.f;
        #pragma unroll
        for (int w = 0; w < NWARP; w++) { St += s_p3[0][w]; At += s_p3[1][w]; Pt += s_p3[2][w]; }
        float sum_p15 = At / (St * sqrtf(St));
        float omega   = (1.0f - sum_p15) / 0.75f;       // alpha*(alpha-1) = 0.75
        g_loss[row] = omega + 2.0f * Pt / St - xt;

        __threadfence();
        int t = atomicAdd(&g_done, 1);
        s_last = (t == NROWS - 1);
    }
    __syncthreads();

    // ============ last block: deterministic mean ============================================
    if (s_last) {
        if (tid == 0) g_done = 0;
        __threadfence();
        float a = 0.f;
        #pragma unroll 4
        for (int i = tid; i < NROWS; i += TA) a += g_loss[i];
        a = warp_sum(a);
        if (lane == 0) s_p3[0][wid] = a;
        __syncthreads();
        if (tid == 0) {
            float tot = 0.f;
            #pragma unroll
            for (int w = 0; w < NWARP; w++) tot += s_p3[0][w];
            out[0] = tot / (float)NROWS;
        }
    }
}

// ============================================================================
extern "C" void kernel_launch(void* const* d_in, const int* in_sizes, int n_in,
                              void* d_out, int out_size)
{
    const float* X      = (const float*)d_in[0];
    const int*   target = (const int*)  d_in[1];
    float*       out    = (float*)d_out;

    fused_kernel<<<NROWS, TA>>>(X, target, out);
}

// round 10
// speedup vs baseline: 1.8223x; 1.0917x over previous
#include <cuda_runtime.h>
#include <cuda_bf16.h>
#include <math_constants.h>

#define D       32000
#define D4      8000
#define NROWS   4096
#define TA      256
#define NWARP   8
#define CHUNK4  1000            // float4s per warp chunk
#define SUBF4   125             // float4s per sub-step
#define NSUB    8
#define CAP_L   24              // per-lane slot capacity (exp 8.35; >=24 -> flagged fallback)
#define WFL     (CAP_L * 32)    // floats per warp region (768)
#define PAD     (17 * 32)       // overrun pad: <=16 slots past clamp + slack
#define NBIS    5
#define NNEWT   4
#define XT      1.5f            // coarse threshold (X scale); valid iff rowmaxX > XT+2 (checked)
#define CHI     0.005590169943749474f   // (1/32000)^0.5

__device__ float g_loss[NROWS];
__device__ int   g_done;        // zero-init; last block resets (graph-replay safe)

__device__ __forceinline__ float warp_sum(float v) {
    #pragma unroll
    for (int o = 16; o; o >>= 1) v += __shfl_xor_sync(0xffffffffu, v, o);
    return v;
}
__device__ __forceinline__ float warp_max(float v) {
    #pragma unroll
    for (int o = 16; o; o >>= 1) v = fmaxf(v, __shfl_xor_sync(0xffffffffu, v, o));
    return v;
}

#define FOR16(OP) OP(c0.x) OP(c0.y) OP(c0.z) OP(c0.w) \
                  OP(c1.x) OP(c1.y) OP(c1.z) OP(c1.w) \
                  OP(c2.x) OP(c2.y) OP(c2.z) OP(c2.w) \
                  OP(c3.x) OP(c3.y) OP(c3.z) OP(c3.w)

__global__ void __launch_bounds__(TA, 5) fused_kernel(const float* __restrict__ X,
                                                      const int*   __restrict__ target,
                                                      float*       __restrict__ out)
{
    __shared__ float s_buf[NWARP * WFL + PAD];   // ~26.7 KB per-lane stride-32 slots
    __shared__ float s_F[2][NWARP], s_G[2][NWARP];
    __shared__ float s_p3[3][NWARP];
    __shared__ float s_max[NWARP];
    __shared__ int   s_fb;
    __shared__ int   s_last;

    const int row  = blockIdx.x;
    const int tid  = threadIdx.x;
    const int lane = tid & 31;
    const int wid  = tid >> 5;

    if (tid == 0) s_fb = 0;
    __syncthreads();

    const float4* __restrict__ Xr4 = reinterpret_cast<const float4*>(X + (size_t)row * D);
    const float*  __restrict__ Xr  = X + (size_t)row * D;
    const float4* __restrict__ W4  = Xr4 + wid * CHUNK4;

    float xt = 0.f;
    if (tid == 0) xt = Xr[target[row]];

    float* const base = s_buf + wid * WFL + lane;   // my column (stride 32 floats)
    float* const plim = base + CAP_L * 32;          // clamp point

    // ============ single-pass filter: 3 inst/elem, own-bank stores, no cross-lane work =====
    const float4 FILL = make_float4(-CUDART_INF_F, -CUDART_INF_F, -CUDART_INF_F, -CUDART_INF_F);
    #define LOADSUB(dst0,dst1,dst2,dst3,sub) do {                        \
        int _b = (sub) * SUBF4;                                          \
        dst0 = W4[_b + lane];                                            \
        dst1 = W4[_b + lane + 32];                                       \
        dst2 = W4[_b + lane + 64];                                       \
        dst3 = (lane + 96 < SUBF4) ? W4[_b + lane + 96] : FILL;          \
    } while (0)

    float4 a0, a1, a2, a3, b0, b1, b2, b3;
    LOADSUB(a0, a1, a2, a3, 0);
    LOADSUB(b0, b1, b2, b3, 1);

    float* p = base;
    #pragma unroll
    for (int sub = 0; sub < NSUB; sub++) {
        float4 c0 = a0, c1 = a1, c2 = a2, c3 = a3;
        a0 = b0; a1 = b1; a2 = b2; a3 = b3;
        if (sub + 2 < NSUB) LOADSUB(b0, b1, b2, b3, sub + 2);

        #define WR(a) { bool q = (a) > XT; if (q) { *p = (a); p += 32; } }
        FOR16(WR)
        #undef WR
        if (p > plim) p = plim;     // clamp ONCE per sub (max +16 slots overrun -> pad/next warp)
    }
    #undef LOADSUB

    const int kl = (int)((p - base) >> 5);   // my candidate count (raw X in my column)
    if (kl >= CAP_L) s_fb = 1;               // benign race; conservative (== full also falls back)

    // ---- row max from candidates (row max always passes the filter when threshold valid) ----
    const int J0 = __reduce_max_sync(0xffffffffu, kl);
    {
        float mx = -CUDART_INF_F;
        for (int j = 0; j < J0; j++) {
            float v = base[j * 32];
            mx = fmaxf(mx, (j < kl) ? v : -CUDART_INF_F);
        }
        mx = warp_max(mx);
        if (lane == 0) s_max[wid] = mx;      // X scale
    }
    __syncthreads();

    float rmaxX = s_max[0];
    #pragma unroll
    for (int w = 1; w < NWARP; w++) rmaxX = fmaxf(rmaxX, s_max[w]);
    const bool fb = (s_fb != 0) || !(rmaxX - 2.0f > XT + 1e-4f);

    if (fb) {    // rare: recompute exact row max block-wide
        __syncthreads();
        float m = -CUDART_INF_F;
        for (int i = tid; i < D; i += TA) m = fmaxf(m, Xr[i]);
        m = warp_max(m);
        if (lane == 0) s_max[wid] = m;
        __syncthreads();
        rmaxX = s_max[0];
        #pragma unroll
        for (int w = 1; w < NWARP; w++) rmaxX = fmaxf(rmaxX, s_max[w]);
    }
    const float rmax = 0.5f * rmaxX;         // exact: max(Xa) = 0.5*max(X)

    // ============ per-lane prune to true candidates (X > rmaxX-2), scale to Xa, pad ========
    int J = 0;
    if (!fb) {
        const float tX = rmaxX - 2.0f - 1e-5f;   // margin only adds zero-contributing elems
        int c2 = 0;
        for (int j = 0; j < J0; j++) {
            float v = base[j * 32];
            if (j < kl && v > tX) { base[c2 * 32] = 0.5f * v; c2++; }
        }
        J = __reduce_max_sync(0xffffffffu, c2);
        for (int j = c2; j < J; j++) base[j * 32] = -1e30f;   // pad -> contributes exactly 0
    }

    // ============ solve: 5 bisection + 4 safeguarded Newton =================================
    const float tau_lo0 = rmax - 1.0f;
    const float tau_hi  = rmax - CHI;
    float tau_lo = tau_lo0;
    float dm = tau_hi - tau_lo;
    float tau_m = tau_lo;
    int pb = 0;

    #pragma unroll 1
    for (int it = 0; it < NBIS + NNEWT; it++) {
        const bool newton = (it >= NBIS);
        float te;
        if (!newton) { dm *= 0.5f; te = tau_lo + dm; }
        else         { te = tau_m; }

        float F = 0.f, G = 0.f;
        if (!fb) {
            for (int j = 0; j < J; j++) {          // uniform trip, conflict-free columns
                float t = fmaxf(base[j * 32] - te, 0.f);
                F = fmaf(t, t, F); G += t;
            }
        } else {
            for (int i = tid; i < D; i += TA) {
                float t = fmaxf(0.5f * Xr[i] - te, 0.f);
                F = fmaf(t, t, F); G += t;
            }
        }
        #pragma unroll
        for (int o = 16; o; o >>= 1) {
            F += __shfl_xor_sync(0xffffffffu, F, o);
            G += __shfl_xor_sync(0xffffffffu, G, o);
        }
        if (lane == 0) { s_F[pb][wid] = F; s_G[pb][wid] = G; }
        __syncthreads();
        float Ft = 0.f, Gt = 0.f;
        #pragma unroll
        for (int w = 0; w < NWARP; w++) { Ft += s_F[pb][w]; Gt += s_G[pb][w]; }
        const float f = Ft - 1.0f;

        if (!newton) {
            if (f >= 0.f) tau_lo = te;        // f(tau_lo) >= 0 invariant
            if (it == NBIS - 1) tau_m = tau_lo;
        } else {
            float tn = te + f / (2.0f * Gt);  // f' = -2G; convex f: Newton from left stays left
            tau_m = fminf(fmaxf(tn, tau_lo0), tau_hi);
        }
        pb ^= 1;
    }

    // ============ final stats at tau_m ======================================================
    float S = 0.f, A15 = 0.f, PX = 0.f;
    if (!fb) {
        for (int j = 0; j < J; j++) {
            float v = base[j * 32];
            float t = fmaxf(v - tau_m, 0.f);
            float pr = t * t;
            S += pr; A15 = fmaf(pr, t, A15); PX = fmaf(pr, v, PX);
        }
    } else {
        for (int i = tid; i < D; i += TA) {
            float v = 0.5f * Xr[i];
            float t = fmaxf(v - tau_m, 0.f);
            float pr = t * t;
            S += pr; A15 = fmaf(pr, t, A15); PX = fmaf(pr, v, PX);
        }
    }
    S = warp_sum(S); A15 = warp_sum(A15); PX = warp_sum(PX);
    if (lane == 0) { s_p3[0][wid] = S; s_p3[1][wid] = A15; s_p3[2][wid] = PX; }
    __syncthreads();

    if (tid == 0) {
        float St = 0.f, At = 0.f, Pt = 0.f;
        #pragma unroll
        for (int w = 0; w < NWARP; w++) { St += s_p3[0][w]; At += s_p3[1][w]; Pt += s_p3[2][w]; }
        float sum_p15 = At / (St * sqrtf(St));
        float omega   = (1.0f - sum_p15) / 0.75f;       // alpha*(alpha-1) = 0.75
        g_loss[row] = omega + 2.0f * Pt / St - xt;

        __threadfence();
        int t = atomicAdd(&g_done, 1);
        s_last = (t == NROWS - 1);
    }
    __syncthreads();

    // ============ last block: deterministic mean ============================================
    if (s_last) {
        if (tid == 0) g_done = 0;
        __threadfence();
        float a = 0.f;
        #pragma unroll 4
        for (int i = tid; i < NROWS; i += TA) a += g_loss[i];
        a = warp_sum(a);
        if (lane == 0) s_p3[0][wid] = a;
        __syncthreads();
        if (tid == 0) {
            float tot = 0.f;
            #pragma unroll
            for (int w = 0; w < NWARP; w++) tot += s_p3[0][w];
            out[0] = tot / (float)NROWS;
        }
    }
}

// ============================================================================
extern "C" void kernel_launch(void* const* d_in, const int* in_sizes, int n_in,
                              void* d_out, int out_size)
{
    const float* X      = (const float*)d_in[0];
    const int*   target = (const int*)  d_in[1];
    float*       out    = (float*)d_out;

    fused_kernel<<<NROWS, TA>>>(X, target, out);
}